// round 12
// baseline (speedup 1.0000x reference)
#include <cuda_runtime.h>
#include <cuda_bf16.h>

// Problem constants
#define B_    64
#define C_    2048
#define HW_   576
#define HW4_  144            // HW_/4 float4 groups per channel row
#define NBLK  16             // tiles per (t,b): 128 channels each
#define CPS   32             // channels per (block, csub)
#define NGRID 2048           // total blocks = NBLK * B_ * 2
#define LUMN  (B_ * HW_)     // 36864 floats per lum buffer

// Scratch (allocation-free rule: __device__ globals; zero at module load).
// Parity ping-pong: launch N accumulates lum[par], zeroes lum[1-par]; the
// finalize thread flips par at the very end (all reads provably precede it).
// Tickets g_t1/g_t2 are NEVER reset: each launch performs exactly 2048 / 64
// increments, so position = count & (N-1). Wrap-free, replay-safe.
__device__ float        g_lum[2][B_][HW_];    // lum_v row-major
__device__ float        g_lumT[2][HW_][B_];   // lum_i TRANSPOSED
__device__ int          g_parity;
__device__ double       g_sum;                // reset by its last reader
__device__ int          g_cnt;
__device__ unsigned int g_t1;                 // block-completion ticket (2048/launch)
__device__ unsigned int g_t2;                 // pair-finalize ticket   (64/launch)

// ---------------------------------------------------------------------------
// SINGLE kernel. grid = (NBLK, B, 2), block = 576, 3 blocks/SM.
// Main body (frozen ~87us stream): float4 loads, smem fold, REDG.F32
//   atomicAdd into g_lum / g_lumT. Zeroes other parity buffer (36 fl/block).
// Tail: every block takes a t1 ticket (after __threadfence -> its lum adds
//   are visible before its ticket). The last 64 ticket-takers become the
//   pair crew: spin until all 2048 ticketed, then run pair-row i (9 p-slices
//   x 64 j, chunked fp32 -> double), mask, reduce, t2-ticket finalize, flip
//   parity, reset g_sum/g_cnt. Labels are int32 (JAX x64 disabled).
// ---------------------------------------------------------------------------
__global__ void __launch_bounds__(576, 3)
k_fused(const float* __restrict__ fv, const float* __restrict__ fi,
        const int* __restrict__ labels, float* __restrict__ out) {
    const int blk  = blockIdx.x;
    const int b    = blockIdx.y;
    const int t    = blockIdx.z;
    const int tid  = threadIdx.x;
    const int q    = tid % HW4_;
    const int csub = tid / HW4_;

    const int par = g_parity;

    // Zero the other parity buffer: 2*LUMN floats over 2048 blocks = 36 each.
    {
        const int blin = blk + NBLK * (b + B_ * t);      // 0..2047
        const int idx  = blin * 36 + tid;
        if (tid < 36) {
            if (idx < LUMN) ((float*)g_lum[1 - par])[idx]         = 0.0f;
            else            ((float*)g_lumT[1 - par])[idx - LUMN] = 0.0f;
        }
    }

    // ---- streaming sum-of-squares (frozen pattern) ----
    const float* __restrict__ f = t ? fi : fv;
    const float4* __restrict__ base = (const float4*)
        (f + ((size_t)b * C_ + (size_t)blk * 128) * HW_)
        + (size_t)csub * CPS * HW4_ + q;

    float ax = 0.f, ay = 0.f, az = 0.f, aw = 0.f;
#pragma unroll 8
    for (int it = 0; it < CPS; ++it) {
        float4 x = base[(size_t)it * HW4_];
        ax = fmaf(x.x, x.x, ax);
        ay = fmaf(x.y, x.y, ay);
        az = fmaf(x.z, x.z, az);
        aw = fmaf(x.w, x.w, aw);
    }

    __shared__ float4 sh[4][HW4_];
    sh[csub][q] = make_float4(ax, ay, az, aw);
    __syncthreads();

    if (csub == 0) {
        float4 a = sh[0][q], c1 = sh[1][q], c2 = sh[2][q], c3 = sh[3][q];
        a.x += c1.x + c2.x + c3.x;
        a.y += c1.y + c2.y + c3.y;
        a.z += c1.z + c2.z + c3.z;
        a.w += c1.w + c2.w + c3.w;
        if (t == 0) {
            float* dst = &g_lum[par][b][4 * q];
            atomicAdd(dst + 0, a.x);
            atomicAdd(dst + 1, a.y);
            atomicAdd(dst + 2, a.z);
            atomicAdd(dst + 3, a.w);
        } else {
            atomicAdd(&g_lumT[par][4 * q + 0][b], a.x);
            atomicAdd(&g_lumT[par][4 * q + 1][b], a.y);
            atomicAdd(&g_lumT[par][4 * q + 2][b], a.z);
            atomicAdd(&g_lumT[par][4 * q + 3][b], a.w);
        }
    }

    // ---- ticket: publish this block's contribution ----
    __threadfence();
    __syncthreads();
    __shared__ unsigned s_tk;
    if (tid == 0) s_tk = atomicAdd(&g_t1, 1u);
    __syncthreads();
    const unsigned my   = s_tk;
    const unsigned pos  = my & (NGRID - 1);          // 0..2047 within launch
    if (pos < NGRID - B_) return;                    // not crew -> done
    const unsigned base_t = my - pos;                // launch epoch base

    // ---- crew: wait for all 2048 blocks of this launch ----
    if (tid == 0) {
        while (atomicAdd(&g_t1, 0u) - base_t < NGRID) __nanosleep(32);
    }
    __syncthreads();
    __threadfence();                                 // acquire

    // ---- pair phase: i = crew row, j = tid%64, slice = tid/64 ----
    const int i  = (int)(pos - (NGRID - B_));        // 0..63
    const int j  = tid % 64;
    const int sl = tid / 64;                         // 0..8

    __shared__ float  s_lv[HW_];
    __shared__ double s_vv[9][64], s_cf[9][64], s_sf[9][64];
    __shared__ double s_red[64];

    s_lv[tid] = g_lum[par][i][tid];
    __syncthreads();

    {
        const int p0 = sl * 64;
        float vv0=0.f, cf0=0.f, sf0=0.f, vv1=0.f, cf1=0.f, sf1=0.f;
#pragma unroll
        for (int k = 0; k < 32; ++k) {
            float lv = s_lv[p0 + k];
            float li = g_lumT[par][p0 + k][j];
            vv0 = fmaf(lv, lv, vv0);
            cf0 = fmaf(lv, li, cf0);
            sf0 = fmaf(li, li, sf0);
        }
#pragma unroll
        for (int k = 32; k < 64; ++k) {
            float lv = s_lv[p0 + k];
            float li = g_lumT[par][p0 + k][j];
            vv1 = fmaf(lv, lv, vv1);
            cf1 = fmaf(lv, li, cf1);
            sf1 = fmaf(li, li, sf1);
        }
        s_vv[sl][j] = (double)vv0 + (double)vv1;     // chunked fp32 -> double
        s_cf[sl][j] = (double)cf0 + (double)cf1;
        s_sf[sl][j] = (double)sf0 + (double)sf1;
    }
    __syncthreads();

    bool   m   = false;
    double mse = 0.0;
    if (sl == 0) {
        double vv = 0.0, cf = 0.0, sf = 0.0;
#pragma unroll
        for (int s = 0; s < 9; ++s) {
            vv += s_vv[s][j]; cf += s_cf[s][j]; sf += s_sf[s][j];
        }
        mse = (vv + sf - 2.0 * cf) / (double)HW_;
        m = (labels[i] == labels[j]) && (i != j);
    }
    const int cnt_i = __syncthreads_count(m);        // only sl==0 can be true

    if (sl == 0) s_red[j] = m ? mse : 0.0;
    __syncthreads();
    for (int s = 32; s > 0; s >>= 1) {
        if (tid < s) s_red[tid] += s_red[tid + s];
        __syncthreads();
    }

    if (tid == 0) {
        atomicAdd(&g_sum, s_red[0]);
        atomicAdd(&g_cnt, cnt_i);
        __threadfence();
        const unsigned tk2 = atomicAdd(&g_t2, 1u);
        if ((tk2 & (B_ - 1)) == B_ - 1) {            // last of this launch's 64
            const double total = atomicAdd(&g_sum, 0.0);  // atomic read
            const int    cnt   = atomicAdd(&g_cnt, 0);
            out[0] = (cnt > 0) ? (float)(total / (double)cnt) : 0.0f;
            g_sum = 0.0; g_cnt = 0;                  // unique last reader resets
            g_parity = par ^ 1;                      // flip for next replay
            __threadfence();
        }
    }
}

extern "C" void kernel_launch(void* const* d_in, const int* in_sizes, int n_in,
                              void* d_out, int out_size) {
    const float* fv     = (const float*)d_in[0];
    const float* fi     = (const float*)d_in[1];
    const int*   labels = (const int*)d_in[2];
    float*       out    = (float*)d_out;

    k_fused<<<dim3(NBLK, B_, 2), 576>>>(fv, fi, labels, out);
}

// round 13
// speedup vs baseline: 1.0899x; 1.0899x over previous
#include <cuda_runtime.h>
#include <cuda_bf16.h>

// Problem constants
#define B_    64
#define C_    2048
#define HW_   576
#define HW4_  144          // HW_/4 float4 groups per channel row
#define NBLK  32           // k1 tiles per (t,b): 64 channels each (short tail)
#define CPS   16           // channels per (block, csub)
#define LUMN  (B_ * HW_)   // 36864 floats per lum buffer

// Scratch (allocation-free rule: __device__ globals; zero at module load).
// Parity ping-pong: k1(N) accumulates buf[par], zeroes buf[1-par];
// k2(N) reads buf[par], flips par. Invariant: buf[par] is zero when k1 starts.
__device__ float        g_lum[2][B_][HW_];    // lum_v row-major
__device__ float        g_lumT[2][HW_][B_];   // lum_i TRANSPOSED
__device__ int          g_parity;
__device__ double       g_sum;
__device__ int          g_cnt;
__device__ unsigned int g_ticket;

// ---------------------------------------------------------------------------
// Kernel 1: streaming sum-of-squares, float4 loads, smem fold, REDG.F32
// atomicAdd of per-tile fold into g_lum / g_lumT (32 adds per address).
// 64-channel tiles halve the ramp-down straggler time vs 128-ch tiles.
// Zeroes other parity buffer (18 floats/block) + scalar reduction state.
// grid = (NBLK, B, 2) = 4096 blocks, block = 576, 3 blocks/SM.
// ---------------------------------------------------------------------------
__global__ void __launch_bounds__(576, 3)
k_lum_partial(const float* __restrict__ fv, const float* __restrict__ fi) {
    const int blk  = blockIdx.x;
    const int b    = blockIdx.y;
    const int t    = blockIdx.z;
    const int tid  = threadIdx.x;
    const int q    = tid % HW4_;
    const int csub = tid / HW4_;

    const int par = g_parity;

    if (blk == 0 && b == 0 && t == 0 && tid == 0) {
        g_sum = 0.0; g_cnt = 0; g_ticket = 0u;
    }

    // Zero the other parity buffer: 2*LUMN floats over 4096 blocks = 18 each.
    {
        const int blin = blk + NBLK * (b + B_ * t);      // 0..4095
        const int idx  = blin * 18 + tid;
        if (tid < 18) {
            if (idx < LUMN) ((float*)g_lum[1 - par])[idx]         = 0.0f;
            else            ((float*)g_lumT[1 - par])[idx - LUMN] = 0.0f;
        }
    }

    const float* __restrict__ f = t ? fi : fv;
    const float4* __restrict__ base = (const float4*)
        (f + ((size_t)b * C_ + (size_t)blk * 64) * HW_)
        + (size_t)csub * CPS * HW4_ + q;

    float ax = 0.f, ay = 0.f, az = 0.f, aw = 0.f;
#pragma unroll 8
    for (int it = 0; it < CPS; ++it) {
        float4 x = base[(size_t)it * HW4_];
        ax = fmaf(x.x, x.x, ax);
        ay = fmaf(x.y, x.y, ay);
        az = fmaf(x.z, x.z, az);
        aw = fmaf(x.w, x.w, aw);
    }

    __shared__ float4 sh[4][HW4_];
    sh[csub][q] = make_float4(ax, ay, az, aw);
    __syncthreads();

    if (csub == 0) {
        float4 a = sh[0][q], c1 = sh[1][q], c2 = sh[2][q], c3 = sh[3][q];
        a.x += c1.x + c2.x + c3.x;
        a.y += c1.y + c2.y + c3.y;
        a.z += c1.z + c2.z + c3.z;
        a.w += c1.w + c2.w + c3.w;
        if (t == 0) {
            float* dst = &g_lum[par][b][4 * q];
            atomicAdd(dst + 0, a.x);
            atomicAdd(dst + 1, a.y);
            atomicAdd(dst + 2, a.z);
            atomicAdd(dst + 3, a.w);
        } else {
            atomicAdd(&g_lumT[par][4 * q + 0][b], a.x);
            atomicAdd(&g_lumT[par][4 * q + 1][b], a.y);
            atomicAdd(&g_lumT[par][4 * q + 2][b], a.z);
            atomicAdd(&g_lumT[par][4 * q + 3][b], a.w);
        }
    }
}

// ---------------------------------------------------------------------------
// Kernel 2: PAIR-ONLY (proven). grid = 64, block = 576.
// i = bid, j = tid%64, slice = tid/64 (9 p-slices). Chunked fp32 -> double.
// Ticket block finalizes the loss and flips parity (all blocks' parity
// reads precede the flip). Labels are int32 (JAX x64 disabled).
// ---------------------------------------------------------------------------
__global__ void __launch_bounds__(576, 2)
k_pair(const int* __restrict__ labels, float* __restrict__ out) {
    const int i   = blockIdx.x;   // 0..63
    const int tid = threadIdx.x;  // 0..575
    const int j   = tid % 64;
    const int sl  = tid / 64;     // 0..8

    const int par = g_parity;

    __shared__ float  s_lv[HW_];
    __shared__ double s_vv[9][64], s_cf[9][64], s_sf[9][64];
    __shared__ double s_red[64];

    s_lv[tid] = g_lum[par][i][tid];
    __syncthreads();

    {
        const int p0 = sl * 64;
        float vv0=0.f, cf0=0.f, sf0=0.f, vv1=0.f, cf1=0.f, sf1=0.f;
#pragma unroll
        for (int k = 0; k < 32; ++k) {
            float lv = s_lv[p0 + k];
            float li = g_lumT[par][p0 + k][j];
            vv0 = fmaf(lv, lv, vv0);
            cf0 = fmaf(lv, li, cf0);
            sf0 = fmaf(li, li, sf0);
        }
#pragma unroll
        for (int k = 32; k < 64; ++k) {
            float lv = s_lv[p0 + k];
            float li = g_lumT[par][p0 + k][j];
            vv1 = fmaf(lv, lv, vv1);
            cf1 = fmaf(lv, li, cf1);
            sf1 = fmaf(li, li, sf1);
        }
        s_vv[sl][j] = (double)vv0 + (double)vv1;   // chunked fp32 -> double
        s_cf[sl][j] = (double)cf0 + (double)cf1;
        s_sf[sl][j] = (double)sf0 + (double)sf1;
    }
    __syncthreads();

    bool   m   = false;
    double mse = 0.0;
    if (sl == 0) {
        double vv = 0.0, cf = 0.0, sf = 0.0;
#pragma unroll
        for (int s = 0; s < 9; ++s) {
            vv += s_vv[s][j]; cf += s_cf[s][j]; sf += s_sf[s][j];
        }
        mse = (vv + sf - 2.0 * cf) / (double)HW_;
        m = (labels[i] == labels[j]) && (i != j);
    }
    const int cnt_i = __syncthreads_count(m);      // only sl==0 can be true

    if (sl == 0) s_red[j] = m ? mse : 0.0;
    __syncthreads();
    for (int s = 32; s > 0; s >>= 1) {
        if (tid < s) s_red[tid] += s_red[tid + s];
        __syncthreads();
    }

    if (tid == 0) {
        atomicAdd(&g_sum, s_red[0]);
        atomicAdd(&g_cnt, cnt_i);
        __threadfence();
        const unsigned tk = atomicAdd(&g_ticket, 1u);
        if (tk == B_ - 1) {
            const double total = atomicAdd(&g_sum, 0.0);  // atomic read
            const int    cnt   = atomicAdd(&g_cnt, 0);
            out[0] = (cnt > 0) ? (float)(total / (double)cnt) : 0.0f;
            g_parity = par ^ 1;                           // flip for next replay
            __threadfence();
        }
    }
}

extern "C" void kernel_launch(void* const* d_in, const int* in_sizes, int n_in,
                              void* d_out, int out_size) {
    const float* fv     = (const float*)d_in[0];
    const float* fi     = (const float*)d_in[1];
    const int*   labels = (const int*)d_in[2];
    float*       out    = (float*)d_out;

    k_lum_partial<<<dim3(NBLK, B_, 2), 576>>>(fv, fi);
    k_pair<<<B_, 576>>>(labels, out);
}